// round 2
// baseline (speedup 1.0000x reference)
#include <cuda_runtime.h>
#include <stdint.h>

// Problem shape (fixed per reference)
#define BB 256
#define NN 1024
#define LL 128
#define MM 512

// Scratch (no allocations allowed): per-row flag + dtype-probe result.
__device__ unsigned char g_flags[BB * NN];
__device__ int g_is64;

// Probe: decide whether the index buffer is int64 or int32.
// If int64: all values are in [0, NN). If int32 read as int64: value =
// lo + hi*2^32 with hi in [0, NN) -> >= 2^32 unless hi == 0.
// P(all 16 probes pass under int32) = (1/1024)^16 ~ 0. Deterministic.
__global__ void probe_dtype_kernel(const long long* __restrict__ idx) {
    int ok = 1;
    #pragma unroll
    for (int i = 0; i < 16; i++) {
        long long v = idx[i];
        if (v < 0 || v >= NN) ok = 0;
    }
    g_is64 = ok;
}

// Scatter flags. One thread per (b, m). Branches on probed dtype.
__global__ void scatter_flags_kernel(const void* __restrict__ idx) {
    int i = blockIdx.x * blockDim.x + threadIdx.x;
    if (i >= BB * MM) return;
    int b = i / MM;
    int n;
    if (g_is64) {
        long long v = ((const long long*)idx)[i];
        n = (int)v;
    } else {
        n = ((const int*)idx)[i];
    }
    // Clamp defensively (avoid OOB corruption if assumptions break).
    if (n >= 0 && n < NN) g_flags[b * NN + n] = 1;
}

// Fill: one warp per 512-B row, one float4 per lane.
//  - unflagged row: straight float4 copy (coalesced)
//  - flagged row:   read only row[0] and row[127], build linspace in regs
__global__ void fill_kernel(const float4* __restrict__ in,
                            float4* __restrict__ out) {
    int gtid = blockIdx.x * blockDim.x + threadIdx.x;
    int row = gtid >> 5;
    int lane = threadIdx.x & 31;
    if (row >= BB * NN) return;

    const float4* src = in  + (size_t)row * 32;
    float4*       dst = out + (size_t)row * 32;

    unsigned char f = g_flags[row];   // warp-uniform broadcast

    if (!f) {
        dst[lane] = src[lane];
    } else {
        const float* srow = (const float*)src;
        float s0 = 0.f, e0 = 0.f;
        if (lane == 0)  s0 = srow[0];
        if (lane == 31) e0 = srow[LL - 1];
        float start = __shfl_sync(0xffffffffu, s0, 0);
        float end   = __shfl_sync(0xffffffffu, e0, 31);
        float delta = end - start;
        const float inv = 1.0f / (float)(LL - 1);

        int base = lane * 4;
        float4 v;
        v.x = start + delta * ((float)(base + 0) * inv);
        v.y = start + delta * ((float)(base + 1) * inv);
        v.z = start + delta * ((float)(base + 2) * inv);
        v.w = start + delta * ((float)(base + 3) * inv);
        dst[lane] = v;
    }
}

extern "C" void kernel_launch(void* const* d_in, const int* in_sizes, int n_in,
                              void* d_out, int out_size) {
    const float* patches = (const float*)d_in[0];
    const void*  midx    = d_in[1];
    float*       out     = (float*)d_out;

    void* flags_ptr = nullptr;
    cudaGetSymbolAddress(&flags_ptr, g_flags);
    cudaMemsetAsync(flags_ptr, 0, BB * NN);

    probe_dtype_kernel<<<1, 1>>>((const long long*)midx);

    {
        int total = BB * MM;
        int threads = 256;
        int blocks = (total + threads - 1) / threads;
        scatter_flags_kernel<<<blocks, threads>>>(midx);
    }

    {
        int total_threads = BB * NN * 32;
        int threads = 256;
        int blocks = total_threads / threads;
        fill_kernel<<<blocks, threads>>>((const float4*)patches, (float4*)out);
    }
}

// round 3
// speedup vs baseline: 1.1413x; 1.1413x over previous
#include <cuda_runtime.h>
#include <stdint.h>

// Problem shape (fixed per reference)
#define BB 256
#define NN 1024
#define LL 128
#define MM 512
#define ROWS_PER_WARP 4

// Scratch (no allocations allowed): per-row flag byte.
__device__ unsigned char g_flags[BB * NN];

// Scatter flags, with the int64/int32 dtype probe folded in.
// Probe: lanes 0..15 each read one int64 slot of the index buffer. If the
// buffer is really int64, every value is in [0, NN). If it is int32 read as
// int64, a slot = lo + hi*2^32 with hi ~ U[0,NN) -> out of range unless
// hi == 0 (P(all 16 pass) = (1/1024)^16 ~ 0). All warps probe the same
// 128 bytes -> L2 broadcast, effectively free. Deterministic.
__global__ void scatter_flags_kernel(const void* __restrict__ idx) {
    int i = blockIdx.x * blockDim.x + threadIdx.x;
    int lane = threadIdx.x & 31;

    long long pv = 0;
    if (lane < 16) pv = ((const long long*)idx)[lane];
    int ok = (pv >= 0 && pv < NN);
    unsigned mask = __ballot_sync(0xffffffffu, ok);
    int is64 = ((mask & 0xFFFFu) == 0xFFFFu);

    if (i >= BB * MM) return;
    int b = i / MM;
    int n;
    if (is64) {
        n = (int)((const long long*)idx)[i];
    } else {
        n = ((const int*)idx)[i];
    }
    if (n >= 0 && n < NN) g_flags[b * NN + n] = 1;  // defensive clamp
}

// Fill: one warp per 4 consecutive rows; one float4 per lane per row.
//  - unflagged row: streaming float4 copy (coalesced, evict-first)
//  - flagged row:   read only row[0] and row[127], build linspace in regs
__global__ void __launch_bounds__(256)
fill_kernel(const float4* __restrict__ in, float4* __restrict__ out) {
    int wid = (blockIdx.x * blockDim.x + threadIdx.x) >> 5;
    int lane = threadIdx.x & 31;
    int row0 = wid * ROWS_PER_WARP;
    if (row0 >= BB * NN) return;

    // One 32-bit flag load covers the warp's 4 rows (row0 % 4 == 0 -> aligned).
    uchar4 f4 = *(const uchar4*)&g_flags[row0];
    const unsigned char* fb = &f4.x;

    const float inv = 1.0f / (float)(LL - 1);

    #pragma unroll
    for (int r = 0; r < ROWS_PER_WARP; r++) {
        int row = row0 + r;
        const float4* src = in  + (size_t)row * 32;
        float4*       dst = out + (size_t)row * 32;

        if (!fb[r]) {
            float4 v = __ldcs(&src[lane]);
            __stcs(&dst[lane], v);
        } else {
            const float* srow = (const float*)src;
            float s0 = 0.f, e0 = 0.f;
            if (lane == 0)  s0 = __ldcs(&srow[0]);
            if (lane == 31) e0 = __ldcs(&srow[LL - 1]);
            float start = __shfl_sync(0xffffffffu, s0, 0);
            float end   = __shfl_sync(0xffffffffu, e0, 31);
            float delta = end - start;

            int base = lane * 4;
            float4 v;
            v.x = start + delta * ((float)(base + 0) * inv);
            v.y = start + delta * ((float)(base + 1) * inv);
            v.z = start + delta * ((float)(base + 2) * inv);
            v.w = start + delta * ((float)(base + 3) * inv);
            __stcs(&dst[lane], v);
        }
    }
}

extern "C" void kernel_launch(void* const* d_in, const int* in_sizes, int n_in,
                              void* d_out, int out_size) {
    const float* patches = (const float*)d_in[0];
    const void*  midx    = d_in[1];
    float*       out     = (float*)d_out;

    void* flags_ptr = nullptr;
    cudaGetSymbolAddress(&flags_ptr, g_flags);
    cudaMemsetAsync(flags_ptr, 0, BB * NN);

    {
        int total = BB * MM;
        int threads = 256;
        int blocks = (total + threads - 1) / threads;
        scatter_flags_kernel<<<blocks, threads>>>(midx);
    }

    {
        int total_warps = (BB * NN) / ROWS_PER_WARP;      // 65536 warps
        int threads = 256;                                 // 8 warps/block
        int blocks = total_warps * 32 / threads;           // 8192 blocks
        fill_kernel<<<blocks, threads>>>((const float4*)patches, (float4*)out);
    }
}

// round 4
// speedup vs baseline: 1.2272x; 1.0752x over previous
#include <cuda_runtime.h>
#include <stdint.h>

// Problem shape (fixed per reference)
#define BB 256
#define NN 1024
#define LL 128
#define MM 512
#define RPW 4   // rows per warp

// Scratch (no allocations allowed): per-row flag BIT (32 KB total).
__device__ unsigned int g_mask[(BB * NN) / 32];

// Scatter flag bits, with the int64/int32 dtype probe folded in.
// Probe: lanes 0..15 read the first 16 int64 slots. True int64 -> all in
// [0, NN). int32-read-as-int64 -> lo + hi*2^32 out of range unless hi==0
// (P(all 16 pass) = (1/1024)^16 ~ 0). Deterministic; L2-broadcast cost.
__global__ void scatter_flags_kernel(const void* __restrict__ idx) {
    int i = blockIdx.x * blockDim.x + threadIdx.x;
    int lane = threadIdx.x & 31;

    long long pv = 0;
    if (lane < 16) pv = ((const long long*)idx)[lane];
    int ok = (pv >= 0 && pv < NN);
    unsigned ballot = __ballot_sync(0xffffffffu, ok);
    int is64 = ((ballot & 0xFFFFu) == 0xFFFFu);

    if (i >= BB * MM) return;
    int b = i / MM;
    int n = is64 ? (int)((const long long*)idx)[i]
                 : ((const int*)idx)[i];
    if (n >= 0 && n < NN) {                 // defensive clamp
        int bit = b * NN + n;
        atomicOr(&g_mask[bit >> 5], 1u << (bit & 31));
    }
}

// Fill: one warp per 4 consecutive rows; one float4 per lane per row.
// Phase 1: issue ALL loads (copy-rows full, flagged-rows endpoints only).
// Phase 2: shuffles + linspace math for flagged rows.
// Phase 3: stores. Front-batched loads -> per-warp MLP ~= 4.
__global__ void __launch_bounds__(256)
fill_kernel(const float4* __restrict__ in, float4* __restrict__ out) {
    int wid = (blockIdx.x * blockDim.x + threadIdx.x) >> 5;
    int lane = threadIdx.x & 31;
    int row0 = wid * RPW;
    if (row0 >= BB * NN) return;

    // One uint covers 32 rows; every warp in the block reads the same word.
    unsigned word = g_mask[row0 >> 5];
    int sh = row0 & 31;

    bool m[RPW];
    #pragma unroll
    for (int r = 0; r < RPW; r++) m[r] = (word >> (sh + r)) & 1u;

    float4 v[RPW];
    float sv[RPW], ev[RPW];

    // ---- Phase 1: all loads, no consumers in between ----
    #pragma unroll
    for (int r = 0; r < RPW; r++) {
        const float* srow = (const float*)(in + (size_t)(row0 + r) * 32);
        if (!m[r]) {
            v[r] = __ldcs((const float4*)srow + lane);
        } else {
            float a = 0.f, b2 = 0.f;
            if (lane == 0)  a  = __ldcs(&srow[0]);
            if (lane == 31) b2 = __ldcs(&srow[LL - 1]);
            sv[r] = a; ev[r] = b2;
        }
    }

    // ---- Phase 2: linspace for flagged rows ----
    const float inv = 1.0f / (float)(LL - 1);
    int base = lane * 4;
    #pragma unroll
    for (int r = 0; r < RPW; r++) {
        if (m[r]) {
            float start = __shfl_sync(0xffffffffu, sv[r], 0);
            float end   = __shfl_sync(0xffffffffu, ev[r], 31);
            float delta = end - start;
            v[r].x = start + delta * ((float)(base + 0) * inv);
            v[r].y = start + delta * ((float)(base + 1) * inv);
            v[r].z = start + delta * ((float)(base + 2) * inv);
            v[r].w = start + delta * ((float)(base + 3) * inv);
        }
    }

    // ---- Phase 3: stores ----
    #pragma unroll
    for (int r = 0; r < RPW; r++) {
        __stcs(out + (size_t)(row0 + r) * 32 + lane, v[r]);
    }
}

extern "C" void kernel_launch(void* const* d_in, const int* in_sizes, int n_in,
                              void* d_out, int out_size) {
    const float* patches = (const float*)d_in[0];
    const void*  midx    = d_in[1];
    float*       out     = (float*)d_out;

    void* mask_ptr = nullptr;
    cudaGetSymbolAddress(&mask_ptr, g_mask);
    cudaMemsetAsync(mask_ptr, 0, (BB * NN) / 32 * sizeof(unsigned int));

    {
        int total = BB * MM;
        int threads = 256;
        int blocks = (total + threads - 1) / threads;
        scatter_flags_kernel<<<blocks, threads>>>(midx);
    }

    {
        int total_warps = (BB * NN) / RPW;      // 65536 warps
        int threads = 256;                      // 8 warps/block
        int blocks = total_warps * 32 / threads;
        fill_kernel<<<blocks, threads>>>((const float4*)patches, (float4*)out);
    }
}

// round 6
// speedup vs baseline: 1.2973x; 1.0571x over previous
#include <cuda_runtime.h>
#include <stdint.h>

// Problem shape (fixed per reference)
#define BB 256
#define NN 1024
#define LL 128
#define MM 512
#define RPW 4              // rows per warp
#define ROWS_PER_BLK 32    // 8 warps * 4 rows; always within one batch

// Single fused kernel: each block covers 32 consecutive rows of one batch.
// It scans that batch's 512 indices to build a 32-bit local flag word,
// then writes its 32 output rows: copy for unflagged, register-generated
// linspace for flagged (reading only the two endpoint elements).
__global__ void __launch_bounds__(256)
fused_kernel(const float4* __restrict__ in, float4* __restrict__ out,
             const void* __restrict__ idx) {
    __shared__ unsigned int s_mask;

    int tid  = threadIdx.x;
    int lane = tid & 31;
    int warp = tid >> 5;
    int row_lo = blockIdx.x * ROWS_PER_BLK;    // block's first GLOBAL row
    int b = row_lo >> 10;                       // batch = row / NN
    int local_lo = row_lo & (NN - 1);           // block's first LOCAL row in batch

    // ---- dtype probe (per warp, reads the same cached 128 B) ----
    // True int64: first 16 values all in [0, NN). int32-read-as-int64:
    // value = lo + hi*2^32, out of range unless hi==0 (P ~ (1/1024)^16 ~ 0).
    long long pv = 0;
    if (lane < 16) pv = ((const long long*)idx)[lane];
    int ok = (pv >= 0 && pv < NN);
    unsigned ballot = __ballot_sync(0xffffffffu, ok);
    int is64 = ((ballot & 0xFFFFu) == 0xFFFFu);

    if (tid == 0) s_mask = 0u;
    __syncthreads();

    // ---- scan this batch's 512 indices; flag hits in [local_lo, local_lo+32) ----
    #pragma unroll
    for (int k = 0; k < MM / 256; k++) {        // 2 indices per thread
        int j = b * MM + tid + k * 256;
        int n = is64 ? (int)((const long long*)idx)[j]
                     : ((const int*)idx)[j];
        unsigned d = (unsigned)(n - local_lo);  // batch-LOCAL comparison
        if (d < (unsigned)ROWS_PER_BLK) atomicOr(&s_mask, 1u << d);
    }
    __syncthreads();

    unsigned word = s_mask;
    int row0 = row_lo + warp * RPW;
    int sh = warp * RPW;

    bool m[RPW];
    #pragma unroll
    for (int r = 0; r < RPW; r++) m[r] = (word >> (sh + r)) & 1u;

    float4 v[RPW];
    float sv[RPW], ev[RPW];

    // ---- Phase 1: front-batched loads (MLP ~= 4) ----
    #pragma unroll
    for (int r = 0; r < RPW; r++) {
        const float* srow = (const float*)(in + (size_t)(row0 + r) * 32);
        if (!m[r]) {
            v[r] = __ldcs((const float4*)srow + lane);
        } else {
            float a = 0.f, e = 0.f;
            if (lane == 0)  a = __ldcs(&srow[0]);
            if (lane == 31) e = __ldcs(&srow[LL - 1]);
            sv[r] = a; ev[r] = e;
        }
    }

    // ---- Phase 2: linspace for flagged rows ----
    const float inv = 1.0f / (float)(LL - 1);
    int base = lane * 4;
    #pragma unroll
    for (int r = 0; r < RPW; r++) {
        if (m[r]) {
            float start = __shfl_sync(0xffffffffu, sv[r], 0);
            float end   = __shfl_sync(0xffffffffu, ev[r], 31);
            float delta = end - start;
            v[r].x = start + delta * ((float)(base + 0) * inv);
            v[r].y = start + delta * ((float)(base + 1) * inv);
            v[r].z = start + delta * ((float)(base + 2) * inv);
            v[r].w = start + delta * ((float)(base + 3) * inv);
        }
    }

    // ---- Phase 3: streaming stores ----
    #pragma unroll
    for (int r = 0; r < RPW; r++) {
        __stcs(out + (size_t)(row0 + r) * 32 + lane, v[r]);
    }
}

extern "C" void kernel_launch(void* const* d_in, const int* in_sizes, int n_in,
                              void* d_out, int out_size) {
    const float* patches = (const float*)d_in[0];
    const void*  midx    = d_in[1];
    float*       out     = (float*)d_out;

    int blocks = (BB * NN) / ROWS_PER_BLK;   // 8192
    fused_kernel<<<blocks, 256>>>((const float4*)patches, (float4*)out, midx);
}

// round 7
// speedup vs baseline: 1.3013x; 1.0031x over previous
#include <cuda_runtime.h>
#include <stdint.h>

// Problem shape (fixed per reference)
#define BB 256
#define NN 1024
#define LL 128
#define MM 512
#define RPW 4              // rows per warp
#define ROWS_PER_BLK 64    // 16 warps * 4 rows; always within one batch
#define THREADS 512

// Single fused kernel: each 512-thread block covers 64 consecutive rows of
// one batch. Exactly one masked-index per thread builds a 64-bit local flag
// mask (2 smem words); then each warp writes 4 rows: float4 copy for
// unflagged rows, register-generated linspace for flagged rows (reading only
// the two endpoint elements).
__global__ void __launch_bounds__(THREADS)
fused_kernel(const float4* __restrict__ in, float4* __restrict__ out,
             const void* __restrict__ idx) {
    __shared__ unsigned int s_mask[2];

    int tid  = threadIdx.x;
    int lane = tid & 31;
    int warp = tid >> 5;
    int row_lo = blockIdx.x * ROWS_PER_BLK;    // block's first GLOBAL row
    int b = row_lo >> 10;                       // batch = row / NN
    int local_lo = row_lo & (NN - 1);           // block's first LOCAL row

    // ---- dtype probe (per warp, same cached 128 B) ----
    // True int64: first 16 values all in [0, NN). int32-read-as-int64:
    // value = lo + hi*2^32, out of range unless hi==0 (P ~ (1/1024)^16 ~ 0).
    long long pv = 0;
    if (lane < 16) pv = ((const long long*)idx)[lane];
    int ok = (pv >= 0 && pv < NN);
    unsigned ballot = __ballot_sync(0xffffffffu, ok);
    int is64 = ((ballot & 0xFFFFu) == 0xFFFFu);

    if (tid < 2) s_mask[tid] = 0u;
    __syncthreads();

    // ---- one index per thread; flag hits in [local_lo, local_lo+64) ----
    {
        int j = b * MM + tid;
        int n = is64 ? (int)((const long long*)idx)[j]
                     : ((const int*)idx)[j];
        unsigned d = (unsigned)(n - local_lo);  // batch-LOCAL comparison
        if (d < (unsigned)ROWS_PER_BLK)
            atomicOr(&s_mask[d >> 5], 1u << (d & 31));
    }
    __syncthreads();

    // Warp w owns rows [row_lo + w*4, +4): bits w*4..w*4+3 of the 64-bit mask.
    unsigned word = s_mask[warp >> 3];
    int sh = (warp & 7) * RPW;
    int row0 = row_lo + warp * RPW;

    bool m[RPW];
    #pragma unroll
    for (int r = 0; r < RPW; r++) m[r] = (word >> (sh + r)) & 1u;

    float4 v[RPW];
    float sv[RPW], ev[RPW];

    // ---- Phase 1: front-batched loads (MLP ~= 4) ----
    #pragma unroll
    for (int r = 0; r < RPW; r++) {
        const float* srow = (const float*)(in + (size_t)(row0 + r) * 32);
        if (!m[r]) {
            v[r] = __ldcs((const float4*)srow + lane);
        } else {
            float a = 0.f, e = 0.f;
            if (lane == 0)  a = __ldcs(&srow[0]);
            if (lane == 31) e = __ldcs(&srow[LL - 1]);
            sv[r] = a; ev[r] = e;
        }
    }

    // ---- Phase 2: linspace for flagged rows ----
    const float inv = 1.0f / (float)(LL - 1);
    int base = lane * 4;
    #pragma unroll
    for (int r = 0; r < RPW; r++) {
        if (m[r]) {
            float start = __shfl_sync(0xffffffffu, sv[r], 0);
            float end   = __shfl_sync(0xffffffffu, ev[r], 31);
            float delta = end - start;
            v[r].x = start + delta * ((float)(base + 0) * inv);
            v[r].y = start + delta * ((float)(base + 1) * inv);
            v[r].z = start + delta * ((float)(base + 2) * inv);
            v[r].w = start + delta * ((float)(base + 3) * inv);
        }
    }

    // ---- Phase 3: streaming stores ----
    #pragma unroll
    for (int r = 0; r < RPW; r++) {
        __stcs(out + (size_t)(row0 + r) * 32 + lane, v[r]);
    }
}

extern "C" void kernel_launch(void* const* d_in, const int* in_sizes, int n_in,
                              void* d_out, int out_size) {
    const float* patches = (const float*)d_in[0];
    const void*  midx    = d_in[1];
    float*       out     = (float*)d_out;

    int blocks = (BB * NN) / ROWS_PER_BLK;   // 4096
    fused_kernel<<<blocks, THREADS>>>((const float4*)patches, (float4*)out, midx);
}